// round 1
// baseline (speedup 1.0000x reference)
#include <cuda_runtime.h>
#include <math.h>
#include <stdint.h>

#define NNODES 8192
#define HDIM   128
#define KNN    16
#define NEDGE  262144
#define NKR    (NNODES*KNN)   // 131072
#define SPLITS 4

// ---------------- scratch (device globals; no allocation allowed) ----------------
static __device__ float g_h[NNODES*HDIM];        // GCN gemm out
static __device__ float g_nbuf[3][NNODES*HDIM];  // n1,n2,n3
static __device__ float g_agg[NNODES*HDIM];
static __device__ float g_sn[NNODES];
static __device__ float g_deg[NNODES];
static __device__ float g_dis[NNODES];
static __device__ float g_nrm[NEDGE];
static __device__ int   g_knn[NKR];
static __device__ float g_F[NKR*256];            // 134 MB gathered edge features
static __device__ float g_H1[NKR*64];
static __device__ float g_H2[NKR*128];
static __device__ float g_e[3][NNODES*HDIM];     // edgeconv outputs
static __device__ float g_r1[NNODES];
static __device__ float g_ptd[SPLITS*NKR];       // partial top-k dists
static __device__ int   g_pti[SPLITS*NKR];       // partial top-k idx

// ---------------- small kernels ----------------
__global__ void k_deg_init() {
    int i = blockIdx.x*blockDim.x + threadIdx.x;
    if (i < NNODES) g_deg[i] = 1.0f;   // self-loop weight 1
}
__global__ void k_deg(const int* __restrict__ ei, const float* __restrict__ ew) {
    int e = blockIdx.x*blockDim.x + threadIdx.x;
    if (e < NEDGE) atomicAdd(&g_deg[ei[NEDGE + e]], ew[e]);
}
__global__ void k_dis() {
    int i = blockIdx.x*blockDim.x + threadIdx.x;
    if (i < NNODES) g_dis[i] = rsqrtf(g_deg[i]);  // deg >= 1 always
}
__global__ void k_norm(const int* __restrict__ ei, const float* __restrict__ ew) {
    int e = blockIdx.x*blockDim.x + threadIdx.x;
    if (e < NEDGE) g_nrm[e] = g_dis[ei[e]] * ew[e] * g_dis[ei[NEDGE + e]];
}
__global__ void k_selfinit() {
    int idx = blockIdx.x*blockDim.x + threadIdx.x;
    int i = idx >> 7;
    float d = g_dis[i];
    g_agg[idx] = d * d * g_h[idx];
}
__global__ void k_scatter(const int* __restrict__ ei) {
    int t = blockIdx.x*blockDim.x + threadIdx.x;   // exactly NEDGE*32 threads
    int e = t >> 5, q = t & 31;
    int s = ei[e], d = ei[NEDGE + e];
    float nr = g_nrm[e];
    float4 v = *(const float4*)&g_h[s*HDIM + q*4];
    float* dst = &g_agg[d*HDIM + q*4];
    atomicAdd(dst + 0, nr * v.x);
    atomicAdd(dst + 1, nr * v.y);
    atomicAdd(dst + 2, nr * v.z);
    atomicAdd(dst + 3, nr * v.w);
}
__global__ void k_biastanh(const float* __restrict__ b, float* __restrict__ out) {
    int idx = blockIdx.x*blockDim.x + threadIdx.x;
    out[idx] = tanhf(g_agg[idx] + b[idx & 127]);
}
__global__ void k_sn(const float* __restrict__ X) {
    int w = threadIdx.x >> 5, lane = threadIdx.x & 31;
    int i = blockIdx.x*8 + w;
    float4 v = *(const float4*)&X[i*HDIM + lane*4];
    float s = v.x*v.x + v.y*v.y + v.z*v.z + v.w*v.w;
    #pragma unroll
    for (int o = 16; o; o >>= 1) s += __shfl_xor_sync(0xffffffffu, s, o);
    if (lane == 0) g_sn[i] = s;
}

// ---------------- statically-indexed top-16 insertion (stays in registers) ----------------
__device__ __forceinline__ void topk_insert(float (&td)[16], int (&ti)[16], float d, int idx) {
    if (d >= td[15]) return;
    #pragma unroll
    for (int p = 15; p > 0; --p) {
        bool sh = td[p-1] > d;
        float nd = sh ? td[p-1] : d;
        int   ni = sh ? ti[p-1] : idx;
        if (td[p] > d) { td[p] = nd; ti[p] = ni; }
    }
    if (td[0] > d) { td[0] = d; ti[0] = idx; }
}

// ---------------- fused Gram + top-k kernel ----------------
#define KNN_SMEM ((128*129 + 2*16*132 + 256)*4)

__global__ __launch_bounds__(256) void k_knn(const float* __restrict__ X) {
    extern __shared__ float sh[];
    float* dist = sh;                    // [128][129]
    float* Aq   = sh + 128*129;          // [16][132]
    float* Bc   = Aq + 16*132;           // [16][132]
    float* snq  = Bc + 16*132;           // [128]
    float* snc  = snq + 128;             // [128]

    const int tid = threadIdx.x;
    const int tx = tid & 15, ty = tid >> 4;
    const int q0 = blockIdx.x * 128;
    const int sp = blockIdx.y;

    float td[16]; int ti[16];
    #pragma unroll
    for (int j = 0; j < 16; j++) { td[j] = 3.0e38f; ti[j] = 0; }

    if (tid < 128) snq[tid] = g_sn[q0 + tid];

    for (int t = 0; t < 16; t++) {
        const int cb = (sp*16 + t) * 128;
        if (tid < 128) snc[tid] = g_sn[cb + tid];

        float acc[8][8];
        #pragma unroll
        for (int m = 0; m < 8; m++)
            #pragma unroll
            for (int n = 0; n < 8; n++) acc[m][n] = 0.f;

        for (int kb = 0; kb < 128; kb += 16) {
            #pragma unroll
            for (int i = 0; i < 2; i++) {
                int f = tid + i*256;
                int r = f >> 2, c4 = f & 3;
                float4 va = *(const float4*)&X[(q0 + r)*HDIM + kb + c4*4];
                Aq[(c4*4+0)*132 + r] = va.x; Aq[(c4*4+1)*132 + r] = va.y;
                Aq[(c4*4+2)*132 + r] = va.z; Aq[(c4*4+3)*132 + r] = va.w;
                float4 vb = *(const float4*)&X[(cb + r)*HDIM + kb + c4*4];
                Bc[(c4*4+0)*132 + r] = vb.x; Bc[(c4*4+1)*132 + r] = vb.y;
                Bc[(c4*4+2)*132 + r] = vb.z; Bc[(c4*4+3)*132 + r] = vb.w;
            }
            __syncthreads();
            #pragma unroll
            for (int kk = 0; kk < 16; kk++) {
                float a[8], b[8];
                *(float4*)&a[0] = *(const float4*)&Aq[kk*132 + ty*8];
                *(float4*)&a[4] = *(const float4*)&Aq[kk*132 + ty*8 + 4];
                *(float4*)&b[0] = *(const float4*)&Bc[kk*132 + tx*8];
                *(float4*)&b[4] = *(const float4*)&Bc[kk*132 + tx*8 + 4];
                #pragma unroll
                for (int m = 0; m < 8; m++)
                    #pragma unroll
                    for (int n = 0; n < 8; n++) acc[m][n] += a[m] * b[n];
            }
            __syncthreads();
        }

        #pragma unroll
        for (int m = 0; m < 8; m++)
            #pragma unroll
            for (int n = 0; n < 8; n++)
                dist[(ty*8+m)*129 + tx*8+n] = snq[ty*8+m] + snc[tx*8+n] - 2.0f*acc[m][n];
        __syncthreads();

        if (tid < 128) {
            float worst = td[15];
            #pragma unroll 4
            for (int c = 0; c < 128; c++) {
                float d = dist[tid*129 + c];
                if (d < worst) { topk_insert(td, ti, d, cb + c); worst = td[15]; }
            }
        }
        __syncthreads();
    }

    if (tid < 128) {
        int q = q0 + tid;
        #pragma unroll
        for (int j = 0; j < 16; j++) {
            g_ptd[(q*SPLITS + sp)*16 + j] = td[j];
            g_pti[(q*SPLITS + sp)*16 + j] = ti[j];
        }
    }
}

__global__ void k_merge() {
    int q = blockIdx.x*blockDim.x + threadIdx.x;
    if (q >= NNODES) return;
    float td[16]; int ti[16];
    #pragma unroll
    for (int j = 0; j < 16; j++) { td[j] = 3.0e38f; ti[j] = 0; }
    for (int s = 0; s < SPLITS; s++) {
        #pragma unroll
        for (int j = 0; j < 16; j++) {
            float d = g_ptd[(q*SPLITS + s)*16 + j];
            int idx = g_pti[(q*SPLITS + s)*16 + j];
            topk_insert(td, ti, d, idx);
        }
    }
    #pragma unroll
    for (int j = 0; j < 16; j++) g_knn[q*KNN + j] = ti[j];
}

__global__ void k_buildF(const float* __restrict__ X) {
    int row = blockIdx.x;           // (i,k) pair
    int c = threadIdx.x;            // 256 threads
    int i = row >> 4;
    int j = g_knn[row];
    float v;
    if (c < 128) v = X[i*HDIM + c];
    else { int cc = c - 128; v = X[j*HDIM + cc] - X[i*HDIM + cc]; }
    g_F[(size_t)row*256 + c] = v;
}

// ---------------- generic SGEMM: C[M,BN] = A[M,Kd] @ B[Kd,BN], BM=128 ----------------
// EPI: 0 = plain, 1 = +bias,relu, 2 = +maxpool over 16-row groups, +bias
template<int BN, int TN, int EPI>
__global__ __launch_bounds__(256) void k_gemm(const float* __restrict__ A,
        const float* __restrict__ B, const float* __restrict__ bias,
        float* __restrict__ C, int Kd)
{
    constexpr int BM = 128, BK = 16, TM = 8;
    __shared__ float As[BK][BM + 4];
    __shared__ float Bs[BK][BN + 4];
    const int tid = threadIdx.x;
    const int tx = tid & 15, ty = tid >> 4;
    const int r0 = blockIdx.x * BM;

    float acc[TM][TN];
    #pragma unroll
    for (int m = 0; m < TM; m++)
        #pragma unroll
        for (int n = 0; n < TN; n++) acc[m][n] = 0.f;

    for (int kb = 0; kb < Kd; kb += BK) {
        #pragma unroll
        for (int i = 0; i < 2; i++) {
            int f = tid + i*256;
            int r = f >> 2, c4 = f & 3;
            float4 v = *(const float4*)&A[(size_t)(r0 + r)*Kd + kb + c4*4];
            As[c4*4+0][r] = v.x; As[c4*4+1][r] = v.y;
            As[c4*4+2][r] = v.z; As[c4*4+3][r] = v.w;
        }
        constexpr int BF4 = BK*BN/4;
        #pragma unroll
        for (int i = 0; i < BF4/256; i++) {
            int f = tid + i*256;
            int r = f / (BN/4), c4 = f % (BN/4);
            *(float4*)&Bs[r][c4*4] = *(const float4*)&B[(size_t)(kb + r)*BN + c4*4];
        }
        __syncthreads();
        #pragma unroll
        for (int kk = 0; kk < BK; kk++) {
            float a[TM], b[TN];
            *(float4*)&a[0] = *(const float4*)&As[kk][ty*TM];
            *(float4*)&a[4] = *(const float4*)&As[kk][ty*TM + 4];
            #pragma unroll
            for (int n = 0; n < TN; n += 4)
                *(float4*)&b[n] = *(const float4*)&Bs[kk][tx*TN + n];
            #pragma unroll
            for (int m = 0; m < TM; m++)
                #pragma unroll
                for (int n = 0; n < TN; n++) acc[m][n] += a[m] * b[n];
        }
        __syncthreads();
    }

    if constexpr (EPI == 2) {
        // rows r0..r0+127 are 8 nodes x 16 knn rows; each thread's 8 rows lie in ONE node
        __shared__ float red[16][BN + 4];
        float mv[TN];
        #pragma unroll
        for (int n = 0; n < TN; n++) {
            mv[n] = acc[0][n];
            #pragma unroll
            for (int m = 1; m < TM; m++) mv[n] = fmaxf(mv[n], acc[m][n]);
        }
        #pragma unroll
        for (int n = 0; n < TN; n++) red[ty][tx*TN + n] = mv[n];
        __syncthreads();
        if ((ty & 1) == 0) {
            int node = blockIdx.x*8 + (ty >> 1);
            #pragma unroll
            for (int n = 0; n < TN; n++) {
                int c = tx*TN + n;
                C[(size_t)node*BN + c] = fmaxf(red[ty][c], red[ty+1][c]) + bias[c];
            }
        }
    } else {
        #pragma unroll
        for (int m = 0; m < TM; m++) {
            size_t r = r0 + ty*TM + m;
            #pragma unroll
            for (int n = 0; n < TN; n += 4) {
                float4 v;
                v.x = acc[m][n]; v.y = acc[m][n+1]; v.z = acc[m][n+2]; v.w = acc[m][n+3];
                if constexpr (EPI == 1) {
                    int c = tx*TN + n;
                    v.x = fmaxf(v.x + bias[c],   0.f);
                    v.y = fmaxf(v.y + bias[c+1], 0.f);
                    v.z = fmaxf(v.z + bias[c+2], 0.f);
                    v.w = fmaxf(v.w + bias[c+3], 0.f);
                }
                *(float4*)&C[r*BN + tx*TN + n] = v;
            }
        }
    }
}

// ---------------- epilogue kernels ----------------
__global__ void k_rownorm() {
    int w = threadIdx.x >> 5, lane = threadIdx.x & 31;
    int i = blockIdx.x*8 + w;
    float4 e = *(const float4*)&g_e[0][i*HDIM + lane*4];
    float4 n = *(const float4*)&g_nbuf[0][i*HDIM + lane*4];
    float a = e.x + n.x, b = e.y + n.y, c = e.z + n.z, d = e.w + n.w;
    float s = a*a + b*b + c*c + d*d;
    #pragma unroll
    for (int o = 16; o; o >>= 1) s += __shfl_xor_sync(0xffffffffu, s, o);
    if (lane == 0) g_r1[i] = sqrtf(s);
}

__global__ void k_final(float* __restrict__ out) {
    int w = threadIdx.x >> 5, lane = threadIdx.x & 31;
    int i = blockIdx.x*8 + w;
    float r = g_r1[i];
    float4 e2 = *(const float4*)&g_e[1][i*HDIM + lane*4];
    float4 n2 = *(const float4*)&g_nbuf[1][i*HDIM + lane*4];
    float4 e3 = *(const float4*)&g_e[2][i*HDIM + lane*4];
    float4 n3 = *(const float4*)&g_nbuf[2][i*HDIM + lane*4];
    float v0 = r * (e2.x + n2.x) * (e3.x + n3.x);
    float v1 = r * (e2.y + n2.y) * (e3.y + n3.y);
    float v2 = r * (e2.z + n2.z) * (e3.z + n3.z);
    float v3 = r * (e2.w + n2.w) * (e3.w + n3.w);
    float m = fmaxf(fmaxf(v0, v1), fmaxf(v2, v3));
    #pragma unroll
    for (int o = 16; o; o >>= 1) m = fmaxf(m, __shfl_xor_sync(0xffffffffu, m, o));
    float s = expf(v0 - m) + expf(v1 - m) + expf(v2 - m) + expf(v3 - m);
    #pragma unroll
    for (int o = 16; o; o >>= 1) s += __shfl_xor_sync(0xffffffffu, s, o);
    float lse = m + logf(s);
    float4 ov = { v0 - lse, v1 - lse, v2 - lse, v3 - lse };
    *(float4*)&out[i*HDIM + lane*4] = ov;
}

// ---------------- launch ----------------
extern "C" void kernel_launch(void* const* d_in, const int* in_sizes, int n_in,
                              void* d_out, int out_size) {
    const float* x  = (const float*)d_in[0];
    const int*   ei = (const int*)  d_in[1];
    const float* ew = (const float*)d_in[2];
    const float* wg[3] = {(const float*)d_in[3], (const float*)d_in[5], (const float*)d_in[7]};
    const float* bg[3] = {(const float*)d_in[4], (const float*)d_in[6], (const float*)d_in[8]};

    float *p_h, *p_n, *p_F, *p_H1, *p_H2, *p_e;
    cudaGetSymbolAddress((void**)&p_h,  g_h);
    cudaGetSymbolAddress((void**)&p_n,  g_nbuf);
    cudaGetSymbolAddress((void**)&p_F,  g_F);
    cudaGetSymbolAddress((void**)&p_H1, g_H1);
    cudaGetSymbolAddress((void**)&p_H2, g_H2);
    cudaGetSymbolAddress((void**)&p_e,  g_e);

    cudaFuncSetAttribute(k_knn, cudaFuncAttributeMaxDynamicSharedMemorySize, KNN_SMEM);

    k_deg_init<<<(NNODES+255)/256, 256>>>();
    k_deg<<<NEDGE/256, 256>>>(ei, ew);
    k_dis<<<(NNODES+255)/256, 256>>>();
    k_norm<<<NEDGE/256, 256>>>(ei, ew);

    const float* cur = x;
    for (int L = 0; L < 3; L++) {
        float* nL = p_n + (size_t)L * NNODES * HDIM;
        float* eL = p_e + (size_t)L * NNODES * HDIM;
        const float* w1 = (const float*)d_in[9 + L*6 + 0];
        const float* b1 = (const float*)d_in[9 + L*6 + 1];
        const float* w2 = (const float*)d_in[9 + L*6 + 2];
        const float* b2 = (const float*)d_in[9 + L*6 + 3];
        const float* w3 = (const float*)d_in[9 + L*6 + 4];
        const float* b3 = (const float*)d_in[9 + L*6 + 5];

        // GCN: h = cur @ wg ; agg = selfloop + scatter ; n = tanh(agg + b)
        k_gemm<128,8,0><<<NNODES/128, 256>>>(cur, wg[L], nullptr, p_h, 128);
        k_selfinit<<<NNODES*HDIM/256, 256>>>();
        k_scatter<<<NEDGE*32/256, 256>>>(ei);
        k_biastanh<<<NNODES*HDIM/256, 256>>>(bg[L], nL);

        // kNN in feature space
        k_sn<<<NNODES/8, 256>>>(nL);
        k_knn<<<dim3(NNODES/128, SPLITS), 256, KNN_SMEM>>>(nL);
        k_merge<<<NNODES/256, 256>>>();

        // EdgeConv MLP as batched GEMMs, maxpool fused in last epilogue
        k_buildF<<<NKR, 256>>>(nL);
        k_gemm<64,4,1> <<<NKR/128, 256>>>(p_F,  w1, b1, p_H1, 256);
        k_gemm<128,8,1><<<NKR/128, 256>>>(p_H1, w2, b2, p_H2, 64);
        k_gemm<128,8,2><<<NKR/128, 256>>>(p_H2, w3, b3, eL,  128);

        cur = nL;
    }

    k_rownorm<<<NNODES/8, 256>>>();
    k_final<<<NNODES/8, 256>>>((float*)d_out);
}

// round 3
// speedup vs baseline: 1.5622x; 1.5622x over previous
#include <cuda_runtime.h>
#include <cuda_bf16.h>
#include <math.h>
#include <stdint.h>

#define NNODES 8192
#define HDIM   128
#define KNN    16
#define NEDGE  262144
#define NKR    (NNODES*KNN)   // 131072
#define KSPL   2              // candidate splits for knn
#define CPS    (NNODES/KSPL)  // 4096 candidates per split
#define TPC    (CPS/128)      // 32 tiles per CTA

// ---------------- scratch (device globals; no allocation allowed) ----------------
static __device__ float g_h[NNODES*HDIM];
static __device__ float g_nbuf[3][NNODES*HDIM];
static __device__ float g_agg[NNODES*HDIM];
static __device__ float g_sn[NNODES];
static __device__ float g_deg[NNODES];
static __device__ float g_dis[NNODES];
static __device__ float g_nrm[NEDGE];
static __device__ int   g_knn[NKR];
static __device__ float g_F[NKR*256];
static __device__ float g_H1[NKR*64];
static __device__ float g_H2[NKR*128];
static __device__ float g_e[3][NNODES*HDIM];
static __device__ float g_r1[NNODES];
static __device__ float g_ptd[KSPL*NKR];
static __device__ int   g_pti[KSPL*NKR];
static __device__ __nv_bfloat16 g_hi[NNODES*HDIM];
static __device__ __nv_bfloat16 g_lo[NNODES*HDIM];

// ---------------- helpers ----------------
__device__ __forceinline__ uint32_t smem_u32(const void* p) {
    uint32_t a;
    asm("{ .reg .u64 t; cvta.to.shared.u64 t, %1; cvt.u32.u64 %0, t; }" : "=r"(a) : "l"(p));
    return a;
}
__device__ __forceinline__ void ldm_x4(uint32_t* r, uint32_t addr) {
    asm volatile("ldmatrix.sync.aligned.m8n8.x4.shared.b16 {%0,%1,%2,%3}, [%4];"
        : "=r"(r[0]), "=r"(r[1]), "=r"(r[2]), "=r"(r[3]) : "r"(addr));
}
__device__ __forceinline__ void mma16816(float* c, const uint32_t* a, const uint32_t* b) {
    asm volatile("mma.sync.aligned.m16n8k16.row.col.f32.bf16.bf16.f32 "
        "{%0,%1,%2,%3}, {%4,%5,%6,%7}, {%8,%9}, {%0,%1,%2,%3};"
        : "+f"(c[0]), "+f"(c[1]), "+f"(c[2]), "+f"(c[3])
        : "r"(a[0]), "r"(a[1]), "r"(a[2]), "r"(a[3]), "r"(b[0]), "r"(b[1]));
}

// ---------------- small kernels ----------------
__global__ void k_deg_init() {
    int i = blockIdx.x*blockDim.x + threadIdx.x;
    if (i < NNODES) g_deg[i] = 1.0f;
}
__global__ void k_deg(const int* __restrict__ ei, const float* __restrict__ ew) {
    int e = blockIdx.x*blockDim.x + threadIdx.x;
    if (e < NEDGE) atomicAdd(&g_deg[ei[NEDGE + e]], ew[e]);
}
__global__ void k_dis() {
    int i = blockIdx.x*blockDim.x + threadIdx.x;
    if (i < NNODES) g_dis[i] = rsqrtf(g_deg[i]);
}
__global__ void k_norm(const int* __restrict__ ei, const float* __restrict__ ew) {
    int e = blockIdx.x*blockDim.x + threadIdx.x;
    if (e < NEDGE) g_nrm[e] = g_dis[ei[e]] * ew[e] * g_dis[ei[NEDGE + e]];
}
__global__ void k_selfinit() {
    int idx = blockIdx.x*blockDim.x + threadIdx.x;
    int i = idx >> 7;
    float d = g_dis[i];
    g_agg[idx] = d * d * g_h[idx];
}
__global__ void k_scatter(const int* __restrict__ ei) {
    int t = blockIdx.x*blockDim.x + threadIdx.x;
    int e = t >> 5, q = t & 31;
    int s = ei[e], d = ei[NEDGE + e];
    float nr = g_nrm[e];
    float4 v = *(const float4*)&g_h[s*HDIM + q*4];
    float* dst = &g_agg[d*HDIM + q*4];
    atomicAdd(dst + 0, nr * v.x);
    atomicAdd(dst + 1, nr * v.y);
    atomicAdd(dst + 2, nr * v.z);
    atomicAdd(dst + 3, nr * v.w);
}
__global__ void k_biastanh(const float* __restrict__ b, float* __restrict__ out) {
    int idx = blockIdx.x*blockDim.x + threadIdx.x;
    out[idx] = tanhf(g_agg[idx] + b[idx & 127]);
}
__global__ void k_sn(const float* __restrict__ X) {
    int w = threadIdx.x >> 5, lane = threadIdx.x & 31;
    int i = blockIdx.x*8 + w;
    float4 v = *(const float4*)&X[i*HDIM + lane*4];
    float s = v.x*v.x + v.y*v.y + v.z*v.z + v.w*v.w;
    #pragma unroll
    for (int o = 16; o; o >>= 1) s += __shfl_xor_sync(0xffffffffu, s, o);
    if (lane == 0) g_sn[i] = s;
}
__global__ void k_split(const float* __restrict__ X) {
    int i = blockIdx.x*blockDim.x + threadIdx.x;
    float v = X[i];
    __nv_bfloat16 h = __float2bfloat16(v);
    g_hi[i] = h;
    g_lo[i] = __float2bfloat16(v - __bfloat162float(h));
}

// ---------------- top-16 insertion (statically indexed, register-resident) ----------------
__device__ __forceinline__ void topk_insert(float (&td)[16], int (&ti)[16], float d, int idx) {
    if (d >= td[15]) return;
    #pragma unroll
    for (int p = 15; p > 0; --p) {
        bool sh = td[p-1] > d;
        float nd = sh ? td[p-1] : d;
        int   ni = sh ? ti[p-1] : idx;
        if (td[p] > d) { td[p] = nd; ti[p] = ni; }
    }
    if (td[0] > d) { td[0] = d; ti[0] = idx; }
}

// ---------------- mma.sync kNN kernel ----------------
// SMEM (bytes): Ah@0 Al@34816 Bh@69632 Bl@104448 dist@139264 snc@206848
#define SSTR    136            // bf16 row stride (272B)
#define TILE_B  (128*SSTR*2)   // 34816 per hi/lo tile
#define SM_AH   0
#define SM_AL   34816
#define SM_BH   69632
#define SM_BL   104448
#define SM_DIST 139264
#define SM_SNC  206848
#define KNN_SMEM 207360

__device__ __forceinline__ void load_tile(char* sm, uint32_t ohi, uint32_t olo,
                                          int node0, int tid) {
    const uint4* HI = (const uint4*)g_hi;
    const uint4* LO = (const uint4*)g_lo;
    #pragma unroll
    for (int it = 0; it < 8; ++it) {
        int idx = tid + it*256;
        int row = idx >> 4;
        int c8  = idx & 15;                    // unit of 8 bf16
        uint32_t so = (uint32_t)(row*SSTR + c8*8)*2;
        size_t gi = ((size_t)(node0 + row)*HDIM + c8*8) >> 3;
        *(uint4*)(sm + ohi + so) = HI[gi];
        *(uint4*)(sm + olo + so) = LO[gi];
    }
}

__global__ void __launch_bounds__(256) k_knn_mma() {
    extern __shared__ char sm[];
    const uint32_t smb = smem_u32(sm);
    const int tid = threadIdx.x, wid = tid >> 5, lane = tid & 31;
    const int wm = wid >> 1, wn = wid & 1;     // warp tile: rows 32*wm, cols 64*wn
    const int q0 = blockIdx.x * 128;
    const int c0 = blockIdx.y * CPS;

    // A (queries) loaded once
    load_tile(sm, SM_AH, SM_AL, q0, tid);

    float td[16]; int ti[16];
    #pragma unroll
    for (int j = 0; j < 16; j++) { td[j] = 3.0e38f; ti[j] = 0; }

    // ldmatrix lane addressing (byte offsets within a tile)
    const uint32_t a_off = (uint32_t)((32*wm + (lane & 15))*SSTR + (lane >> 4)*8) * 2;
    const uint32_t b_off = (uint32_t)((64*wn + (lane >> 4)*8 + (lane & 7))*SSTR
                                      + ((lane >> 3) & 1)*8) * 2;
    float* dist = (float*)(sm + SM_DIST);
    float* snc  = (float*)(sm + SM_SNC);

    for (int t = 0; t < TPC; ++t) {
        __syncthreads();   // previous tile's scan done before overwriting B
        load_tile(sm, SM_BH, SM_BL, c0 + t*128, tid);
        if (tid < 128) snc[tid] = g_sn[c0 + t*128 + tid];
        __syncthreads();

        float acc[2][8][4];
        #pragma unroll
        for (int mf = 0; mf < 2; mf++)
            #pragma unroll
            for (int nf = 0; nf < 8; nf++)
                #pragma unroll
                for (int v = 0; v < 4; v++) acc[mf][nf][v] = 0.f;

        #pragma unroll
        for (int term = 0; term < 3; ++term) {
            const uint32_t abase = smb + (term == 2 ? SM_AL : SM_AH) + a_off;
            const uint32_t bbase = smb + (term == 1 ? SM_BL : SM_BH) + b_off;
            #pragma unroll
            for (int ks = 0; ks < 8; ++ks) {
                uint32_t a0[4], a1[4];
                ldm_x4(a0, abase + ks*32);
                ldm_x4(a1, abase + ks*32 + 16*SSTR*2);
                #pragma unroll
                for (int nf = 0; nf < 4; ++nf) {
                    uint32_t b[4];
                    ldm_x4(b, bbase + ks*32 + nf*16*SSTR*2);
                    mma16816(acc[0][nf*2],   a0, b);
                    mma16816(acc[0][nf*2+1], a0, b + 2);
                    mma16816(acc[1][nf*2],   a1, b);
                    mma16816(acc[1][nf*2+1], a1, b + 2);
                }
            }
        }

        // store dot products to smem dist tile
        {
            const int r0 = 32*wm + (lane >> 2);
            const int cb = 64*wn + (lane & 3)*2;
            #pragma unroll
            for (int mf = 0; mf < 2; mf++)
                #pragma unroll
                for (int nf = 0; nf < 8; nf++) {
                    float2 lo = { acc[mf][nf][0], acc[mf][nf][1] };
                    float2 hi = { acc[mf][nf][2], acc[mf][nf][3] };
                    *(float2*)&dist[(r0 + mf*16    )*132 + cb + nf*8] = lo;
                    *(float2*)&dist[(r0 + mf*16 + 8)*132 + cb + nf*8] = hi;
                }
        }
        __syncthreads();

        if (tid < 128) {
            const int cbase = c0 + t*128;
            float worst = td[15];
            #pragma unroll 4
            for (int c = 0; c < 128; c++) {
                float d = snc[c] - 2.0f*dist[tid*132 + c];
                if (d < worst) { topk_insert(td, ti, d, cbase + c); worst = td[15]; }
            }
        }
    }

    if (tid < 128) {
        int q = q0 + tid;
        #pragma unroll
        for (int j = 0; j < 16; j++) {
            g_ptd[(q*KSPL + blockIdx.y)*16 + j] = td[j];
            g_pti[(q*KSPL + blockIdx.y)*16 + j] = ti[j];
        }
    }
}

__global__ void k_merge() {
    int q = blockIdx.x*blockDim.x + threadIdx.x;
    if (q >= NNODES) return;
    float td[16]; int ti[16];
    #pragma unroll
    for (int j = 0; j < 16; j++) { td[j] = 3.0e38f; ti[j] = 0; }
    for (int s = 0; s < KSPL; s++) {
        #pragma unroll
        for (int j = 0; j < 16; j++) {
            float d = g_ptd[(q*KSPL + s)*16 + j];
            int idx = g_pti[(q*KSPL + s)*16 + j];
            topk_insert(td, ti, d, idx);
        }
    }
    #pragma unroll
    for (int j = 0; j < 16; j++) g_knn[q*KNN + j] = ti[j];
}

__global__ void k_buildF(const float* __restrict__ X) {
    int row = blockIdx.x;
    int c = threadIdx.x;
    int i = row >> 4;
    int j = g_knn[row];
    float v;
    if (c < 128) v = X[i*HDIM + c];
    else { int cc = c - 128; v = X[j*HDIM + cc] - X[i*HDIM + cc]; }
    g_F[(size_t)row*256 + c] = v;
}

// ---------------- SIMT SGEMM for GCN + MLP ----------------
template<int BN, int TN, int EPI>
__global__ __launch_bounds__(256) void k_gemm(const float* __restrict__ A,
        const float* __restrict__ B, const float* __restrict__ bias,
        float* __restrict__ C, int Kd)
{
    constexpr int BM = 128, BK = 16, TM = 8;
    __shared__ float As[BK][BM + 4];
    __shared__ float Bs[BK][BN + 4];
    const int tid = threadIdx.x;
    const int tx = tid & 15, ty = tid >> 4;
    const int r0 = blockIdx.x * BM;

    float acc[TM][TN];
    #pragma unroll
    for (int m = 0; m < TM; m++)
        #pragma unroll
        for (int n = 0; n < TN; n++) acc[m][n] = 0.f;

    for (int kb = 0; kb < Kd; kb += BK) {
        #pragma unroll
        for (int i = 0; i < 2; i++) {
            int f = tid + i*256;
            int r = f >> 2, c4 = f & 3;
            float4 v = *(const float4*)&A[(size_t)(r0 + r)*Kd + kb + c4*4];
            As[c4*4+0][r] = v.x; As[c4*4+1][r] = v.y;
            As[c4*4+2][r] = v.z; As[c4*4+3][r] = v.w;
        }
        constexpr int BF4 = BK*BN/4;
        #pragma unroll
        for (int i = 0; i < BF4/256; i++) {
            int f = tid + i*256;
            int r = f / (BN/4), c4 = f % (BN/4);
            *(float4*)&Bs[r][c4*4] = *(const float4*)&B[(size_t)(kb + r)*BN + c4*4];
        }
        __syncthreads();
        #pragma unroll
        for (int kk = 0; kk < BK; kk++) {
            float a[TM], b[TN];
            *(float4*)&a[0] = *(const float4*)&As[kk][ty*TM];
            *(float4*)&a[4] = *(const float4*)&As[kk][ty*TM + 4];
            #pragma unroll
            for (int n = 0; n < TN; n += 4)
                *(float4*)&b[n] = *(const float4*)&Bs[kk][tx*TN + n];
            #pragma unroll
            for (int m = 0; m < TM; m++)
                #pragma unroll
                for (int n = 0; n < TN; n++) acc[m][n] += a[m] * b[n];
        }
        __syncthreads();
    }

    if constexpr (EPI == 2) {
        __shared__ float red[16][BN + 4];
        float mv[TN];
        #pragma unroll
        for (int n = 0; n < TN; n++) {
            mv[n] = acc[0][n];
            #pragma unroll
            for (int m = 1; m < TM; m++) mv[n] = fmaxf(mv[n], acc[m][n]);
        }
        #pragma unroll
        for (int n = 0; n < TN; n++) red[ty][tx*TN + n] = mv[n];
        __syncthreads();
        if ((ty & 1) == 0) {
            int node = blockIdx.x*8 + (ty >> 1);
            #pragma unroll
            for (int n = 0; n < TN; n++) {
                int c = tx*TN + n;
                C[(size_t)node*BN + c] = fmaxf(red[ty][c], red[ty+1][c]) + bias[c];
            }
        }
    } else {
        #pragma unroll
        for (int m = 0; m < TM; m++) {
            size_t r = r0 + ty*TM + m;
            #pragma unroll
            for (int n = 0; n < TN; n += 4) {
                float4 v;
                v.x = acc[m][n]; v.y = acc[m][n+1]; v.z = acc[m][n+2]; v.w = acc[m][n+3];
                if constexpr (EPI == 1) {
                    int c = tx*TN + n;
                    v.x = fmaxf(v.x + bias[c],   0.f);
                    v.y = fmaxf(v.y + bias[c+1], 0.f);
                    v.z = fmaxf(v.z + bias[c+2], 0.f);
                    v.w = fmaxf(v.w + bias[c+3], 0.f);
                }
                *(float4*)&C[r*BN + tx*TN + n] = v;
            }
        }
    }
}

// ---------------- epilogue kernels ----------------
__global__ void k_rownorm() {
    int w = threadIdx.x >> 5, lane = threadIdx.x & 31;
    int i = blockIdx.x*8 + w;
    float4 e = *(const float4*)&g_e[0][i*HDIM + lane*4];
    float4 n = *(const float4*)&g_nbuf[0][i*HDIM + lane*4];
    float a = e.x + n.x, b = e.y + n.y, c = e.z + n.z, d = e.w + n.w;
    float s = a*a + b*b + c*c + d*d;
    #pragma unroll
    for (int o = 16; o; o >>= 1) s += __shfl_xor_sync(0xffffffffu, s, o);
    if (lane == 0) g_r1[i] = sqrtf(s);
}

__global__ void k_final(float* __restrict__ out) {
    int w = threadIdx.x >> 5, lane = threadIdx.x & 31;
    int i = blockIdx.x*8 + w;
    float r = g_r1[i];
    float4 e2 = *(const float4*)&g_e[1][i*HDIM + lane*4];
    float4 n2 = *(const float4*)&g_nbuf[1][i*HDIM + lane*4];
    float4 e3 = *(const float4*)&g_e[2][i*HDIM + lane*4];
    float4 n3 = *(const float4*)&g_nbuf[2][i*HDIM + lane*4];
    float v0 = r * (e2.x + n2.x) * (e3.x + n3.x);
    float v1 = r * (e2.y + n2.y) * (e3.y + n3.y);
    float v2 = r * (e2.z + n2.z) * (e3.z + n3.z);
    float v3 = r * (e2.w + n2.w) * (e3.w + n3.w);
    float m = fmaxf(fmaxf(v0, v1), fmaxf(v2, v3));
    #pragma unroll
    for (int o = 16; o; o >>= 1) m = fmaxf(m, __shfl_xor_sync(0xffffffffu, m, o));
    float s = expf(v0 - m) + expf(v1 - m) + expf(v2 - m) + expf(v3 - m);
    #pragma unroll
    for (int o = 16; o; o >>= 1) s += __shfl_xor_sync(0xffffffffu, s, o);
    float lse = m + logf(s);
    float4 ov = { v0 - lse, v1 - lse, v2 - lse, v3 - lse };
    *(float4*)&out[i*HDIM + lane*4] = ov;
}

// ---------------- launch ----------------
extern "C" void kernel_launch(void* const* d_in, const int* in_sizes, int n_in,
                              void* d_out, int out_size) {
    const float* x  = (const float*)d_in[0];
    const int*   ei = (const int*)  d_in[1];
    const float* ew = (const float*)d_in[2];
    const float* wg[3] = {(const float*)d_in[3], (const float*)d_in[5], (const float*)d_in[7]};
    const float* bg[3] = {(const float*)d_in[4], (const float*)d_in[6], (const float*)d_in[8]};

    float *p_h, *p_n, *p_F, *p_H1, *p_H2, *p_e;
    cudaGetSymbolAddress((void**)&p_h,  g_h);
    cudaGetSymbolAddress((void**)&p_n,  g_nbuf);
    cudaGetSymbolAddress((void**)&p_F,  g_F);
    cudaGetSymbolAddress((void**)&p_H1, g_H1);
    cudaGetSymbolAddress((void**)&p_H2, g_H2);
    cudaGetSymbolAddress((void**)&p_e,  g_e);

    cudaFuncSetAttribute(k_knn_mma, cudaFuncAttributeMaxDynamicSharedMemorySize, KNN_SMEM);

    k_deg_init<<<(NNODES+255)/256, 256>>>();
    k_deg<<<NEDGE/256, 256>>>(ei, ew);
    k_dis<<<(NNODES+255)/256, 256>>>();
    k_norm<<<NEDGE/256, 256>>>(ei, ew);

    const float* cur = x;
    for (int L = 0; L < 3; L++) {
        float* nL = p_n + (size_t)L * NNODES * HDIM;
        float* eL = p_e + (size_t)L * NNODES * HDIM;
        const float* w1 = (const float*)d_in[9 + L*6 + 0];
        const float* b1 = (const float*)d_in[9 + L*6 + 1];
        const float* w2 = (const float*)d_in[9 + L*6 + 2];
        const float* b2 = (const float*)d_in[9 + L*6 + 3];
        const float* w3 = (const float*)d_in[9 + L*6 + 4];
        const float* b3 = (const float*)d_in[9 + L*6 + 5];

        // GCN
        k_gemm<128,8,0><<<NNODES/128, 256>>>(cur, wg[L], nullptr, p_h, 128);
        k_selfinit<<<NNODES*HDIM/256, 256>>>();
        k_scatter<<<NEDGE*32/256, 256>>>(ei);
        k_biastanh<<<NNODES*HDIM/256, 256>>>(bg[L], nL);

        // kNN: sq-norms + bf16 split + HMMA Gram + top-k
        k_sn<<<NNODES/8, 256>>>(nL);
        k_split<<<NNODES*HDIM/256, 256>>>(nL);
        k_knn_mma<<<dim3(NNODES/128, KSPL), 256, KNN_SMEM>>>();
        k_merge<<<NNODES/256, 256>>>();

        // EdgeConv MLP
        k_buildF<<<NKR, 256>>>(nL);
        k_gemm<64,4,1> <<<NKR/128, 256>>>(p_F,  w1, b1, p_H1, 256);
        k_gemm<128,8,1><<<NKR/128, 256>>>(p_H1, w2, b2, p_H2, 64);
        k_gemm<128,8,2><<<NKR/128, 256>>>(p_H2, w3, b3, eL,  128);

        cur = nL;
    }

    k_rownorm<<<NNODES/8, 256>>>();
    k_final<<<NNODES/8, 256>>>((float*)d_out);
}

// round 5
// speedup vs baseline: 1.9308x; 1.2360x over previous
#include <cuda_runtime.h>
#include <cuda_bf16.h>
#include <math.h>
#include <stdint.h>

#define NNODES 8192
#define HDIM   128
#define KNN    16
#define NEDGE  262144
#define NKR    (NNODES*KNN)   // 131072
#define KSPL   2
#define CPS    (NNODES/KSPL)
#define TPC    (CPS/128)

// ---------------- scratch (device globals) ----------------
static __device__ float g_h[NNODES*HDIM];
static __device__ float g_nbuf[3][NNODES*HDIM];
static __device__ float g_agg[NNODES*HDIM];
static __device__ float g_sn[NNODES];
static __device__ float g_deg[NNODES];
static __device__ float g_dis[NNODES];
static __device__ float g_nrm[NEDGE];
static __device__ int   g_knn[NKR];
static __device__ float g_e[3][NNODES*HDIM];
static __device__ float g_r1[NNODES];
static __device__ float g_ptd[KSPL*NKR];
static __device__ int   g_pti[KSPL*NKR];
static __device__ __nv_bfloat16 g_hi[NNODES*HDIM];
static __device__ __nv_bfloat16 g_lo[NNODES*HDIM];
static __device__ float g_R[NNODES*64];
static __device__ float g_S[NNODES*64];
static __device__ float g_wd[128*64];

// ---------------- helpers ----------------
__device__ __forceinline__ uint32_t smem_u32(const void* p) {
    uint32_t a;
    asm("{ .reg .u64 t; cvta.to.shared.u64 t, %1; cvt.u32.u64 %0, t; }" : "=r"(a) : "l"(p));
    return a;
}
__device__ __forceinline__ void ldm_x4(uint32_t* r, uint32_t addr) {
    asm volatile("ldmatrix.sync.aligned.m8n8.x4.shared.b16 {%0,%1,%2,%3}, [%4];"
        : "=r"(r[0]), "=r"(r[1]), "=r"(r[2]), "=r"(r[3]) : "r"(addr));
}
__device__ __forceinline__ void mma16816(float* c, const uint32_t* a, const uint32_t* b) {
    asm volatile("mma.sync.aligned.m16n8k16.row.col.f32.bf16.bf16.f32 "
        "{%0,%1,%2,%3}, {%4,%5,%6,%7}, {%8,%9}, {%0,%1,%2,%3};"
        : "+f"(c[0]), "+f"(c[1]), "+f"(c[2]), "+f"(c[3])
        : "r"(a[0]), "r"(a[1]), "r"(a[2]), "r"(a[3]), "r"(b[0]), "r"(b[1]));
}

// ---------------- small kernels ----------------
__global__ void k_deg_init() {
    int i = blockIdx.x*blockDim.x + threadIdx.x;
    if (i < NNODES) g_deg[i] = 1.0f;
}
__global__ void k_deg(const int* __restrict__ ei, const float* __restrict__ ew) {
    int e = blockIdx.x*blockDim.x + threadIdx.x;
    if (e < NEDGE) atomicAdd(&g_deg[ei[NEDGE + e]], ew[e]);
}
__global__ void k_dis() {
    int i = blockIdx.x*blockDim.x + threadIdx.x;
    if (i < NNODES) g_dis[i] = rsqrtf(g_deg[i]);
}
__global__ void k_norm(const int* __restrict__ ei, const float* __restrict__ ew) {
    int e = blockIdx.x*blockDim.x + threadIdx.x;
    if (e < NEDGE) g_nrm[e] = g_dis[ei[e]] * ew[e] * g_dis[ei[NEDGE + e]];
}
__global__ void k_selfinit() {
    int idx = blockIdx.x*blockDim.x + threadIdx.x;
    int i = idx >> 7;
    float d = g_dis[i];
    g_agg[idx] = d * d * g_h[idx];
}
__global__ void k_scatter(const int* __restrict__ ei) {
    int t = blockIdx.x*blockDim.x + threadIdx.x;
    int e = t >> 5, q = t & 31;
    int s = ei[e], d = ei[NEDGE + e];
    float nr = g_nrm[e];
    float4 v = *(const float4*)&g_h[s*HDIM + q*4];
    float* dst = &g_agg[d*HDIM + q*4];
    atomicAdd(dst + 0, nr * v.x);
    atomicAdd(dst + 1, nr * v.y);
    atomicAdd(dst + 2, nr * v.z);
    atomicAdd(dst + 3, nr * v.w);
}
__global__ void k_biastanh(const float* __restrict__ b, float* __restrict__ out) {
    int idx = blockIdx.x*blockDim.x + threadIdx.x;
    out[idx] = tanhf(g_agg[idx] + b[idx & 127]);
}
__global__ void k_sn(const float* __restrict__ X) {
    int w = threadIdx.x >> 5, lane = threadIdx.x & 31;
    int i = blockIdx.x*8 + w;
    float4 v = *(const float4*)&X[i*HDIM + lane*4];
    float s = v.x*v.x + v.y*v.y + v.z*v.z + v.w*v.w;
    #pragma unroll
    for (int o = 16; o; o >>= 1) s += __shfl_xor_sync(0xffffffffu, s, o);
    if (lane == 0) g_sn[i] = s;
}
__global__ void k_split(const float* __restrict__ X) {
    int i = blockIdx.x*blockDim.x + threadIdx.x;
    float v = X[i];
    __nv_bfloat16 h = __float2bfloat16(v);
    g_hi[i] = h;
    g_lo[i] = __float2bfloat16(v - __bfloat162float(h));
}
__global__ void k_wdiff(const float* __restrict__ w1) {
    int i = blockIdx.x*blockDim.x + threadIdx.x;   // 8192 threads: [128][64]
    g_wd[i] = w1[i] - w1[128*64 + i];
}

// ---------------- top-16 insertion ----------------
__device__ __forceinline__ void topk_insert(float (&td)[16], int (&ti)[16], float d, int idx) {
    if (d >= td[15]) return;
    #pragma unroll
    for (int p = 15; p > 0; --p) {
        bool sh = td[p-1] > d;
        float nd = sh ? td[p-1] : d;
        int   ni = sh ? ti[p-1] : idx;
        if (td[p] > d) { td[p] = nd; ti[p] = ni; }
    }
    if (td[0] > d) { td[0] = d; ti[0] = idx; }
}

// ---------------- mma.sync kNN kernel ----------------
#define SSTR    136
#define SM_AH   0
#define SM_AL   34816
#define SM_BH   69632
#define SM_BL   104448
#define SM_DIST 139264
#define SM_SNC  206848
#define KNN_SMEM 207360

__device__ __forceinline__ void load_tile(char* sm, uint32_t ohi, uint32_t olo,
                                          int node0, int tid) {
    const uint4* HI = (const uint4*)g_hi;
    const uint4* LO = (const uint4*)g_lo;
    #pragma unroll
    for (int it = 0; it < 8; ++it) {
        int idx = tid + it*256;
        int row = idx >> 4;
        int c8  = idx & 15;
        uint32_t so = (uint32_t)(row*SSTR + c8*8)*2;
        size_t gi = ((size_t)(node0 + row)*HDIM + c8*8) >> 3;
        *(uint4*)(sm + ohi + so) = HI[gi];
        *(uint4*)(sm + olo + so) = LO[gi];
    }
}

__global__ void __launch_bounds__(256) k_knn_mma() {
    extern __shared__ char sm[];
    const uint32_t smb = smem_u32(sm);
    const int tid = threadIdx.x, wid = tid >> 5, lane = tid & 31;
    const int wm = wid >> 1, wn = wid & 1;
    const int q0 = blockIdx.x * 128;
    const int c0 = blockIdx.y * CPS;

    load_tile(sm, SM_AH, SM_AL, q0, tid);

    float td[16]; int ti[16];
    #pragma unroll
    for (int j = 0; j < 16; j++) { td[j] = 3.0e38f; ti[j] = 0; }

    const uint32_t a_off = (uint32_t)((32*wm + (lane & 15))*SSTR + (lane >> 4)*8) * 2;
    const uint32_t b_off = (uint32_t)((64*wn + (lane >> 4)*8 + (lane & 7))*SSTR
                                      + ((lane >> 3) & 1)*8) * 2;
    float* dist = (float*)(sm + SM_DIST);
    float* snc  = (float*)(sm + SM_SNC);

    for (int t = 0; t < TPC; ++t) {
        __syncthreads();
        load_tile(sm, SM_BH, SM_BL, c0 + t*128, tid);
        if (tid < 128) snc[tid] = g_sn[c0 + t*128 + tid];
        __syncthreads();

        float acc[2][8][4];
        #pragma unroll
        for (int mf = 0; mf < 2; mf++)
            #pragma unroll
            for (int nf = 0; nf < 8; nf++)
                #pragma unroll
                for (int v = 0; v < 4; v++) acc[mf][nf][v] = 0.f;

        #pragma unroll
        for (int term = 0; term < 3; ++term) {
            const uint32_t abase = smb + (term == 2 ? SM_AL : SM_AH) + a_off;
            const uint32_t bbase = smb + (term == 1 ? SM_BL : SM_BH) + b_off;
            #pragma unroll
            for (int ks = 0; ks < 8; ++ks) {
                uint32_t a0[4], a1[4];
                ldm_x4(a0, abase + ks*32);
                ldm_x4(a1, abase + ks*32 + 16*SSTR*2);
                #pragma unroll
                for (int nf = 0; nf < 4; ++nf) {
                    uint32_t b[4];
                    ldm_x4(b, bbase + ks*32 + nf*16*SSTR*2);
                    mma16816(acc[0][nf*2],   a0, b);
                    mma16816(acc[0][nf*2+1], a0, b + 2);
                    mma16816(acc[1][nf*2],   a1, b);
                    mma16816(acc[1][nf*2+1], a1, b + 2);
                }
            }
        }

        {
            const int r0 = 32*wm + (lane >> 2);
            const int cb = 64*wn + (lane & 3)*2;
            #pragma unroll
            for (int mf = 0; mf < 2; mf++)
                #pragma unroll
                for (int nf = 0; nf < 8; nf++) {
                    float2 lo = { acc[mf][nf][0], acc[mf][nf][1] };
                    float2 hi = { acc[mf][nf][2], acc[mf][nf][3] };
                    *(float2*)&dist[(r0 + mf*16    )*132 + cb + nf*8] = lo;
                    *(float2*)&dist[(r0 + mf*16 + 8)*132 + cb + nf*8] = hi;
                }
        }
        __syncthreads();

        if (tid < 128) {
            const int cbase = c0 + t*128;
            float worst = td[15];
            #pragma unroll 4
            for (int c = 0; c < 128; c++) {
                float d = snc[c] - 2.0f*dist[tid*132 + c];
                if (d < worst) { topk_insert(td, ti, d, cbase + c); worst = td[15]; }
            }
        }
    }

    if (tid < 128) {
        int q = q0 + tid;
        #pragma unroll
        for (int j = 0; j < 16; j++) {
            g_ptd[(q*KSPL + blockIdx.y)*16 + j] = td[j];
            g_pti[(q*KSPL + blockIdx.y)*16 + j] = ti[j];
        }
    }
}

__global__ void k_merge() {
    int q = blockIdx.x*blockDim.x + threadIdx.x;
    if (q >= NNODES) return;
    float td[16]; int ti[16];
    #pragma unroll
    for (int j = 0; j < 16; j++) { td[j] = 3.0e38f; ti[j] = 0; }
    for (int s = 0; s < KSPL; s++) {
        #pragma unroll
        for (int j = 0; j < 16; j++) {
            float d = g_ptd[(q*KSPL + s)*16 + j];
            int idx = g_pti[(q*KSPL + s)*16 + j];
            topk_insert(td, ti, d, idx);
        }
    }
    #pragma unroll
    for (int j = 0; j < 16; j++) g_knn[q*KNN + j] = ti[j];
}

// ---------------- fused EdgeConv MLP kernel ----------------
// H1 = relu(R[i] + S[j])  [128 rows x 64]
// H2 = relu(H1 @ W2 + b2) [128 x 128]
// E[node] = max_16(H2 @ W3) + b3
// smem floats: H1s [128][68] @0, H2s [128][132] @8704, Bs [16][132] @25600,
//              red [16][132] @27712, jidx(int) @29824
#define EDGE_SMEM ((29824 + 128) * 4)

__global__ void __launch_bounds__(256) k_edge(
        const float* __restrict__ R, const float* __restrict__ S,
        const float* __restrict__ w2, const float* __restrict__ b2,
        const float* __restrict__ w3, const float* __restrict__ b3,
        float* __restrict__ E)
{
    extern __shared__ float es[];
    float* H1s = es;            // stride 68
    float* H2s = es + 8704;     // stride 132
    float* Bs  = es + 25600;    // stride 132
    float* red = es + 27712;    // stride 132
    int* jidx  = (int*)(es + 29824);

    const int tid = threadIdx.x;
    const int tx = tid & 15, ty = tid >> 4;
    const int r0 = blockIdx.x * 128;

    if (tid < 128) jidx[tid] = g_knn[r0 + tid];
    __syncthreads();

    // ---- stage 0: gather H1 ----
    {
        int row = tid >> 1;
        int cb = (tid & 1) * 32;
        int i = (r0 + row) >> 4;
        int j = jidx[row];
        const float* Ri = &R[(size_t)i*64 + cb];
        const float* Sj = &S[(size_t)j*64 + cb];
        #pragma unroll
        for (int c = 0; c < 32; c += 4) {
            float4 rv = *(const float4*)(Ri + c);
            float4 sv = *(const float4*)(Sj + c);
            float4 h;
            h.x = fmaxf(rv.x + sv.x, 0.f);
            h.y = fmaxf(rv.y + sv.y, 0.f);
            h.z = fmaxf(rv.z + sv.z, 0.f);
            h.w = fmaxf(rv.w + sv.w, 0.f);
            *(float4*)&H1s[row*68 + cb + c] = h;
        }
    }
    __syncthreads();

    float acc[8][8];
    #pragma unroll
    for (int m = 0; m < 8; m++)
        #pragma unroll
        for (int n = 0; n < 8; n++) acc[m][n] = 0.f;

    // ---- stage 1: GEMM2 (K=64) ----
    for (int kb = 0; kb < 64; kb += 16) {
        #pragma unroll
        for (int i = 0; i < 2; i++) {
            int f = tid + i*256;
            int r = f >> 5, c4 = f & 31;
            *(float4*)&Bs[r*132 + c4*4] = *(const float4*)&w2[(kb + r)*128 + c4*4];
        }
        __syncthreads();
        #pragma unroll
        for (int kk = 0; kk < 16; kk++) {
            float a[8], b[8];
            #pragma unroll
            for (int m = 0; m < 8; m++) a[m] = H1s[(ty*8+m)*68 + kb + kk];
            *(float4*)&b[0] = *(const float4*)&Bs[kk*132 + tx*8];
            *(float4*)&b[4] = *(const float4*)&Bs[kk*132 + tx*8 + 4];
            #pragma unroll
            for (int m = 0; m < 8; m++)
                #pragma unroll
                for (int n = 0; n < 8; n++) acc[m][n] += a[m] * b[n];
        }
        __syncthreads();
    }

    // bias + relu, stage into H2s
    {
        float4 b20 = *(const float4*)&b2[tx*8];
        float4 b21 = *(const float4*)&b2[tx*8 + 4];
        float bb[8] = {b20.x, b20.y, b20.z, b20.w, b21.x, b21.y, b21.z, b21.w};
        #pragma unroll
        for (int m = 0; m < 8; m++) {
            float4 v0, v1;
            v0.x = fmaxf(acc[m][0] + bb[0], 0.f);
            v0.y = fmaxf(acc[m][1] + bb[1], 0.f);
            v0.z = fmaxf(acc[m][2] + bb[2], 0.f);
            v0.w = fmaxf(acc[m][3] + bb[3], 0.f);
            v1.x = fmaxf(acc[m][4] + bb[4], 0.f);
            v1.y = fmaxf(acc[m][5] + bb[5], 0.f);
            v1.z = fmaxf(acc[m][6] + bb[6], 0.f);
            v1.w = fmaxf(acc[m][7] + bb[7], 0.f);
            *(float4*)&H2s[(ty*8+m)*132 + tx*8]     = v0;
            *(float4*)&H2s[(ty*8+m)*132 + tx*8 + 4] = v1;
        }
    }
    __syncthreads();

    // ---- stage 2: GEMM3 (K=128) ----
    #pragma unroll
    for (int m = 0; m < 8; m++)
        #pragma unroll
        for (int n = 0; n < 8; n++) acc[m][n] = 0.f;

    for (int kb = 0; kb < 128; kb += 16) {
        #pragma unroll
        for (int i = 0; i < 2; i++) {
            int f = tid + i*256;
            int r = f >> 5, c4 = f & 31;
            *(float4*)&Bs[r*132 + c4*4] = *(const float4*)&w3[(kb + r)*128 + c4*4];
        }
        __syncthreads();
        #pragma unroll
        for (int kk = 0; kk < 16; kk++) {
            float a[8], b[8];
            #pragma unroll
            for (int m = 0; m < 8; m++) a[m] = H2s[(ty*8+m)*132 + kb + kk];
            *(float4*)&b[0] = *(const float4*)&Bs[kk*132 + tx*8];
            *(float4*)&b[4] = *(const float4*)&Bs[kk*132 + tx*8 + 4];
            #pragma unroll
            for (int m = 0; m < 8; m++)
                #pragma unroll
                for (int n = 0; n < 8; n++) acc[m][n] += a[m] * b[n];
        }
        __syncthreads();
    }

    // ---- max over 16-row groups + bias ----
    {
        float mv[8];
        #pragma unroll
        for (int n = 0; n < 8; n++) {
            mv[n] = acc[0][n];
            #pragma unroll
            for (int m = 1; m < 8; m++) mv[n] = fmaxf(mv[n], acc[m][n]);
        }
        #pragma unroll
        for (int n = 0; n < 8; n++) red[ty*132 + tx*8 + n] = mv[n];
        __syncthreads();
        if ((ty & 1) == 0) {
            int node = blockIdx.x*8 + (ty >> 1);
            #pragma unroll
            for (int n = 0; n < 8; n++) {
                int c = tx*8 + n;
                E[(size_t)node*128 + c] = fmaxf(red[ty*132 + c], red[(ty+1)*132 + c]) + b3[c];
            }
        }
    }
}

// ---------------- SIMT SGEMM (GCN + R/S precompute) ----------------
// EPI: 0 plain, 1 bias+relu, 3 bias only
template<int BN, int TN, int EPI>
__global__ __launch_bounds__(256) void k_gemm(const float* __restrict__ A,
        const float* __restrict__ B, const float* __restrict__ bias,
        float* __restrict__ C, int Kd)
{
    constexpr int BM = 128, BK = 16, TM = 8;
    __shared__ float As[BK][BM + 4];
    __shared__ float Bs[BK][BN + 4];
    const int tid = threadIdx.x;
    const int tx = tid & 15, ty = tid >> 4;
    const int r0 = blockIdx.x * BM;

    float acc[TM][TN];
    #pragma unroll
    for (int m = 0; m < TM; m++)
        #pragma unroll
        for (int n = 0; n < TN; n++) acc[m][n] = 0.f;

    for (int kb = 0; kb < Kd; kb += BK) {
        #pragma unroll
        for (int i = 0; i < 2; i++) {
            int f = tid + i*256;
            int r = f >> 2, c4 = f & 3;
            float4 v = *(const float4*)&A[(size_t)(r0 + r)*Kd + kb + c4*4];
            As[c4*4+0][r] = v.x; As[c4*4+1][r] = v.y;
            As[c4*4+2][r] = v.z; As[c4*4+3][r] = v.w;
        }
        constexpr int BF4 = BK*BN/4;
        #pragma unroll
        for (int i = 0; i < BF4/256; i++) {
            int f = tid + i*256;
            int r = f / (BN/4), c4 = f % (BN/4);
            *(float4*)&Bs[r][c4*4] = *(const float4*)&B[(size_t)(kb + r)*BN + c4*4];
        }
        __syncthreads();
        #pragma unroll
        for (int kk = 0; kk < BK; kk++) {
            float a[TM], b[TN];
            *(float4*)&a[0] = *(const float4*)&As[kk][ty*TM];
            *(float4*)&a[4] = *(const float4*)&As[kk][ty*TM + 4];
            #pragma unroll
            for (int n = 0; n < TN; n += 4)
                *(float4*)&b[n] = *(const float4*)&Bs[kk][tx*TN + n];
            #pragma unroll
            for (int m = 0; m < TM; m++)
                #pragma unroll
                for (int n = 0; n < TN; n++) acc[m][n] += a[m] * b[n];
        }
        __syncthreads();
    }

    #pragma unroll
    for (int m = 0; m < TM; m++) {
        size_t r = r0 + ty*TM + m;
        #pragma unroll
        for (int n = 0; n < TN; n += 4) {
            float4 v;
            v.x = acc[m][n]; v.y = acc[m][n+1]; v.z = acc[m][n+2]; v.w = acc[m][n+3];
            if constexpr (EPI == 1 || EPI == 3) {
                int c = tx*TN + n;
                v.x += bias[c]; v.y += bias[c+1]; v.z += bias[c+2]; v.w += bias[c+3];
                if constexpr (EPI == 1) {
                    v.x = fmaxf(v.x, 0.f); v.y = fmaxf(v.y, 0.f);
                    v.z = fmaxf(v.z, 0.f); v.w = fmaxf(v.w, 0.f);
                }
            }
            *(float4*)&C[r*BN + tx*TN + n] = v;
        }
    }
}

// ---------------- epilogue kernels ----------------
__global__ void k_rownorm() {
    int w = threadIdx.x >> 5, lane = threadIdx.x & 31;
    int i = blockIdx.x*8 + w;
    float4 e = *(const float4*)&g_e[0][i*HDIM + lane*4];
    float4 n = *(const float4*)&g_nbuf[0][i*HDIM + lane*4];
    float a = e.x + n.x, b = e.y + n.y, c = e.z + n.z, d = e.w + n.w;
    float s = a*a + b*b + c*c + d*d;
    #pragma unroll
    for (int o = 16; o; o >>= 1) s += __shfl_xor_sync(0xffffffffu, s, o);
    if (lane == 0) g_r1[i] = sqrtf(s);
}

__global__ void k_final(float* __restrict__ out) {
    int w = threadIdx.x >> 5, lane = threadIdx.x & 31;
    int i = blockIdx.x*8 + w;
    float r = g_r1[i];
    float4 e2 = *(const float4*)&g_e[1][i*HDIM + lane*4];
    float4 n2 = *(const float4*)&g_nbuf[1][i*HDIM + lane*4];
    float4 e3 = *(const float4*)&g_e[2][i*HDIM + lane*4];
    float4 n3 = *(const float4*)&g_nbuf[2][i*HDIM + lane*4];
    float v0 = r * (e2.x + n2.x) * (e3.x + n3.x);
    float v1 = r * (e2.y + n2.y) * (e3.y + n3.y);
    float v2 = r * (e2.z + n2.z) * (e3.z + n3.z);
    float v3 = r * (e2.w + n2.w) * (e3.w + n3.w);
    float m = fmaxf(fmaxf(v0, v1), fmaxf(v2, v3));
    #pragma unroll
    for (int o = 16; o; o >>= 1) m = fmaxf(m, __shfl_xor_sync(0xffffffffu, m, o));
    float s = expf(v0 - m) + expf(v1 - m) + expf(v2 - m) + expf(v3 - m);
    #pragma unroll
    for (int o = 16; o; o >>= 1) s += __shfl_xor_sync(0xffffffffu, s, o);
    float lse = m + logf(s);
    float4 ov = { v0 - lse, v1 - lse, v2 - lse, v3 - lse };
    *(float4*)&out[i*HDIM + lane*4] = ov;
}

// ---------------- launch ----------------
extern "C" void kernel_launch(void* const* d_in, const int* in_sizes, int n_in,
                              void* d_out, int out_size) {
    const float* x  = (const float*)d_in[0];
    const int*   ei = (const int*)  d_in[1];
    const float* ew = (const float*)d_in[2];
    const float* wg[3] = {(const float*)d_in[3], (const float*)d_in[5], (const float*)d_in[7]};
    const float* bg[3] = {(const float*)d_in[4], (const float*)d_in[6], (const float*)d_in[8]};

    float *p_h, *p_n, *p_e, *p_R, *p_S, *p_wd;
    cudaGetSymbolAddress((void**)&p_h,  g_h);
    cudaGetSymbolAddress((void**)&p_n,  g_nbuf);
    cudaGetSymbolAddress((void**)&p_e,  g_e);
    cudaGetSymbolAddress((void**)&p_R,  g_R);
    cudaGetSymbolAddress((void**)&p_S,  g_S);
    cudaGetSymbolAddress((void**)&p_wd, g_wd);

    cudaFuncSetAttribute(k_knn_mma, cudaFuncAttributeMaxDynamicSharedMemorySize, KNN_SMEM);
    cudaFuncSetAttribute(k_edge,    cudaFuncAttributeMaxDynamicSharedMemorySize, EDGE_SMEM);

    k_deg_init<<<(NNODES+255)/256, 256>>>();
    k_deg<<<NEDGE/256, 256>>>(ei, ew);
    k_dis<<<(NNODES+255)/256, 256>>>();
    k_norm<<<NEDGE/256, 256>>>(ei, ew);

    const float* cur = x;
    for (int L = 0; L < 3; L++) {
        float* nL = p_n + (size_t)L * NNODES * HDIM;
        float* eL = p_e + (size_t)L * NNODES * HDIM;
        const float* w1 = (const float*)d_in[9 + L*6 + 0];
        const float* b1 = (const float*)d_in[9 + L*6 + 1];
        const float* w2 = (const float*)d_in[9 + L*6 + 2];
        const float* b2 = (const float*)d_in[9 + L*6 + 3];
        const float* w3 = (const float*)d_in[9 + L*6 + 4];
        const float* b3 = (const float*)d_in[9 + L*6 + 5];

        // GCN
        k_gemm<128,8,0><<<NNODES/128, 256>>>(cur, wg[L], nullptr, p_h, 128);
        k_selfinit<<<NNODES*HDIM/256, 256>>>();
        k_scatter<<<NEDGE*32/256, 256>>>(ei);
        k_biastanh<<<NNODES*HDIM/256, 256>>>(bg[L], nL);

        // kNN
        k_sn<<<NNODES/8, 256>>>(nL);
        k_split<<<NNODES*HDIM/256, 256>>>(nL);
        k_knn_mma<<<dim3(NNODES/128, KSPL), 256, KNN_SMEM>>>();
        k_merge<<<NNODES/256, 256>>>();

        // EdgeConv: R/S precompute + fused gather/GEMM2/GEMM3/max
        k_wdiff<<<8192/256, 256>>>(w1);
        k_gemm<64,4,3><<<NNODES/128, 256>>>(nL, p_wd,        b1,      p_R, 128);
        k_gemm<64,4,0><<<NNODES/128, 256>>>(nL, w1 + 128*64, nullptr, p_S, 128);
        k_edge<<<NKR/128, 256, EDGE_SMEM>>>(p_R, p_S, w2, b2, w3, b3, eL);

        cur = nL;
    }

    k_rownorm<<<NNODES/8, 256>>>();
    k_final<<<NNODES/8, 256>>>((float*)d_out);
}

// round 6
// speedup vs baseline: 2.4225x; 1.2547x over previous
#include <cuda_runtime.h>
#include <cuda_bf16.h>
#include <math.h>
#include <stdint.h>

#define NNODES 8192
#define HDIM   128
#define KNN    16
#define NEDGE  262144
#define NKR    (NNODES*KNN)
#define KSPL   2
#define CPS    (NNODES/KSPL)
#define TPC    (CPS/128)

// ---------------- scratch (device globals) ----------------
static __device__ float g_h[NNODES*HDIM];
static __device__ float g_nbuf[3][NNODES*HDIM];
static __device__ float g_sn[NNODES];
static __device__ float g_deg[NNODES];
static __device__ float g_dis[NNODES];
static __device__ int   g_knn[NKR];
static __device__ float g_e[3][NNODES*HDIM];
static __device__ float g_r1[NNODES];
static __device__ float g_ptd[KSPL*NKR];
static __device__ int   g_pti[KSPL*NKR];
static __device__ __nv_bfloat16 g_hi[NNODES*HDIM];
static __device__ __nv_bfloat16 g_lo[NNODES*HDIM];
static __device__ float g_R[NNODES*64];
static __device__ float g_S[NNODES*64];
static __device__ float g_wd[128*64];
// CSR
static __device__ int   g_cnt[NNODES];
static __device__ int   g_off[NNODES+1];
static __device__ int   g_cur[NNODES];
static __device__ int   g_esrc[NEDGE];
static __device__ float g_enrm[NEDGE];

// ---------------- helpers ----------------
__device__ __forceinline__ uint32_t smem_u32(const void* p) {
    uint32_t a;
    asm("{ .reg .u64 t; cvta.to.shared.u64 t, %1; cvt.u32.u64 %0, t; }" : "=r"(a) : "l"(p));
    return a;
}
__device__ __forceinline__ void ldm_x4(uint32_t* r, uint32_t addr) {
    asm volatile("ldmatrix.sync.aligned.m8n8.x4.shared.b16 {%0,%1,%2,%3}, [%4];"
        : "=r"(r[0]), "=r"(r[1]), "=r"(r[2]), "=r"(r[3]) : "r"(addr));
}
__device__ __forceinline__ void mma16816(float* c, const uint32_t* a, const uint32_t* b) {
    asm volatile("mma.sync.aligned.m16n8k16.row.col.f32.bf16.bf16.f32 "
        "{%0,%1,%2,%3}, {%4,%5,%6,%7}, {%8,%9}, {%0,%1,%2,%3};"
        : "+f"(c[0]), "+f"(c[1]), "+f"(c[2]), "+f"(c[3])
        : "r"(a[0]), "r"(a[1]), "r"(a[2]), "r"(a[3]), "r"(b[0]), "r"(b[1]));
}
__device__ __forceinline__ __nv_bfloat162 split_hi2(float a, float b) {
    __nv_bfloat162 r; r.x = __float2bfloat16(a); r.y = __float2bfloat16(b); return r;
}
__device__ __forceinline__ __nv_bfloat162 split_lo2(float a, float b, __nv_bfloat162 h) {
    __nv_bfloat162 r;
    r.x = __float2bfloat16(a - __bfloat162float(h.x));
    r.y = __float2bfloat16(b - __bfloat162float(h.y));
    return r;
}

// ---------------- graph prep kernels ----------------
__global__ void k_deg_init() {
    int i = blockIdx.x*blockDim.x + threadIdx.x;
    if (i < NNODES) { g_deg[i] = 1.0f; g_cnt[i] = 0; }
}
__global__ void k_deg(const int* __restrict__ ei, const float* __restrict__ ew) {
    int e = blockIdx.x*blockDim.x + threadIdx.x;
    if (e < NEDGE) {
        atomicAdd(&g_deg[ei[NEDGE + e]], ew[e]);
        atomicAdd(&g_cnt[ei[NEDGE + e]], 1);
    }
}
__global__ void k_dis() {
    int i = blockIdx.x*blockDim.x + threadIdx.x;
    if (i < NNODES) g_dis[i] = rsqrtf(g_deg[i]);
}
__global__ void k_scan() {   // single block, 1024 threads, scans g_cnt[8192]
    __shared__ int ws[32];
    int t = threadIdx.x, lane = t & 31, w = t >> 5;
    int base = t*8;
    int v[8], s = 0;
    #pragma unroll
    for (int i = 0; i < 8; i++) { v[i] = s; s += g_cnt[base + i]; }
    int x = s;
    #pragma unroll
    for (int o = 1; o < 32; o <<= 1) {
        int y = __shfl_up_sync(0xffffffffu, x, o);
        if (lane >= o) x += y;
    }
    if (lane == 31) ws[w] = x;
    __syncthreads();
    if (w == 0) {
        int y = ws[lane];
        #pragma unroll
        for (int o = 1; o < 32; o <<= 1) {
            int z = __shfl_up_sync(0xffffffffu, y, o);
            if (lane >= o) y += z;
        }
        ws[lane] = y;
    }
    __syncthreads();
    int off = x - s + (w ? ws[w-1] : 0);
    #pragma unroll
    for (int i = 0; i < 8; i++) { g_off[base + i] = off + v[i]; g_cur[base + i] = off + v[i]; }
    if (t == 1023) g_off[NNODES] = off + s;
}
__global__ void k_place(const int* __restrict__ ei, const float* __restrict__ ew) {
    int e = blockIdx.x*blockDim.x + threadIdx.x;
    if (e < NEDGE) {
        int s = ei[e], d = ei[NEDGE + e];
        int slot = atomicAdd(&g_cur[d], 1);
        g_esrc[slot] = s;
        g_enrm[slot] = g_dis[s] * ew[e] * g_dis[d];
    }
}

// ---------------- fused GCN aggregate + tanh + sn + split ----------------
__global__ void __launch_bounds__(256) k_gather(const float* __restrict__ bg,
                                                float* __restrict__ out) {
    int wid = threadIdx.x >> 5, lane = threadIdx.x & 31;
    int node = blockIdx.x*8 + wid;
    int c = lane*4;
    float dsq = g_dis[node]; dsq *= dsq;
    float4 v = *(const float4*)&g_h[node*HDIM + c];
    v.x *= dsq; v.y *= dsq; v.z *= dsq; v.w *= dsq;
    int beg = g_off[node], end = g_off[node+1];
    for (int p = beg; p < end; ++p) {
        int s = g_esrc[p];
        float nr = g_enrm[p];
        float4 hv = *(const float4*)&g_h[s*HDIM + c];
        v.x += nr*hv.x; v.y += nr*hv.y; v.z += nr*hv.z; v.w += nr*hv.w;
    }
    float4 b = *(const float4*)&bg[c];
    float t0 = tanhf(v.x + b.x), t1 = tanhf(v.y + b.y);
    float t2 = tanhf(v.z + b.z), t3 = tanhf(v.w + b.w);
    *(float4*)&out[node*HDIM + c] = make_float4(t0, t1, t2, t3);
    float ss = t0*t0 + t1*t1 + t2*t2 + t3*t3;
    #pragma unroll
    for (int o = 16; o; o >>= 1) ss += __shfl_xor_sync(0xffffffffu, ss, o);
    if (lane == 0) g_sn[node] = ss;
    __nv_bfloat162 h01 = split_hi2(t0, t1), h23 = split_hi2(t2, t3);
    __nv_bfloat162 l01 = split_lo2(t0, t1, h01), l23 = split_lo2(t2, t3, h23);
    *(__nv_bfloat162*)&g_hi[node*HDIM + c]     = h01;
    *(__nv_bfloat162*)&g_hi[node*HDIM + c + 2] = h23;
    *(__nv_bfloat162*)&g_lo[node*HDIM + c]     = l01;
    *(__nv_bfloat162*)&g_lo[node*HDIM + c + 2] = l23;
}

__global__ void k_wdiff(const float* __restrict__ w1) {
    int i = blockIdx.x*blockDim.x + threadIdx.x;
    g_wd[i] = w1[i] - w1[128*64 + i];
}

// ---------------- top-16 insertion ----------------
__device__ __forceinline__ void topk_insert(float (&td)[16], int (&ti)[16], float d, int idx) {
    if (d >= td[15]) return;
    #pragma unroll
    for (int p = 15; p > 0; --p) {
        bool sh = td[p-1] > d;
        float nd = sh ? td[p-1] : d;
        int   ni = sh ? ti[p-1] : idx;
        if (td[p] > d) { td[p] = nd; ti[p] = ni; }
    }
    if (td[0] > d) { td[0] = d; ti[0] = idx; }
}

// ---------------- mma.sync kNN kernel ----------------
#define SSTR    136
#define SM_AH   0
#define SM_AL   34816
#define SM_BH   69632
#define SM_BL   104448
#define SM_DIST 139264
#define SM_SNC  206848
#define KNN_SMEM 207360

__device__ __forceinline__ void load_tile(char* sm, uint32_t ohi, uint32_t olo,
                                          int node0, int tid) {
    const uint4* HI = (const uint4*)g_hi;
    const uint4* LO = (const uint4*)g_lo;
    #pragma unroll
    for (int it = 0; it < 8; ++it) {
        int idx = tid + it*256;
        int row = idx >> 4;
        int c8  = idx & 15;
        uint32_t so = (uint32_t)(row*SSTR + c8*8)*2;
        size_t gi = ((size_t)(node0 + row)*HDIM + c8*8) >> 3;
        *(uint4*)(sm + ohi + so) = HI[gi];
        *(uint4*)(sm + olo + so) = LO[gi];
    }
}

__global__ void __launch_bounds__(256) k_knn_mma() {
    extern __shared__ char sm[];
    const uint32_t smb = smem_u32(sm);
    const int tid = threadIdx.x, wid = tid >> 5, lane = tid & 31;
    const int wm = wid >> 1, wn = wid & 1;
    const int q0 = blockIdx.x * 128;
    const int c0 = blockIdx.y * CPS;

    load_tile(sm, SM_AH, SM_AL, q0, tid);

    float td[16]; int ti[16];
    #pragma unroll
    for (int j = 0; j < 16; j++) { td[j] = 3.0e38f; ti[j] = 0; }

    const uint32_t a_off = (uint32_t)((32*wm + (lane & 15))*SSTR + (lane >> 4)*8) * 2;
    const uint32_t b_off = (uint32_t)((64*wn + (lane >> 4)*8 + (lane & 7))*SSTR
                                      + ((lane >> 3) & 1)*8) * 2;
    float* dist = (float*)(sm + SM_DIST);
    float* snc  = (float*)(sm + SM_SNC);

    for (int t = 0; t < TPC; ++t) {
        __syncthreads();
        load_tile(sm, SM_BH, SM_BL, c0 + t*128, tid);
        if (tid < 128) snc[tid] = g_sn[c0 + t*128 + tid];
        __syncthreads();

        float acc[2][8][4];
        #pragma unroll
        for (int mf = 0; mf < 2; mf++)
            #pragma unroll
            for (int nf = 0; nf < 8; nf++)
                #pragma unroll
                for (int v = 0; v < 4; v++) acc[mf][nf][v] = 0.f;

        #pragma unroll
        for (int term = 0; term < 3; ++term) {
            const uint32_t abase = smb + (term == 2 ? SM_AL : SM_AH) + a_off;
            const uint32_t bbase = smb + (term == 1 ? SM_BL : SM_BH) + b_off;
            #pragma unroll
            for (int ks = 0; ks < 8; ++ks) {
                uint32_t a0[4], a1[4];
                ldm_x4(a0, abase + ks*32);
                ldm_x4(a1, abase + ks*32 + 16*SSTR*2);
                #pragma unroll
                for (int nf = 0; nf < 4; ++nf) {
                    uint32_t b[4];
                    ldm_x4(b, bbase + ks*32 + nf*16*SSTR*2);
                    mma16816(acc[0][nf*2],   a0, b);
                    mma16816(acc[0][nf*2+1], a0, b + 2);
                    mma16816(acc[1][nf*2],   a1, b);
                    mma16816(acc[1][nf*2+1], a1, b + 2);
                }
            }
        }

        {
            const int r0 = 32*wm + (lane >> 2);
            const int cb = 64*wn + (lane & 3)*2;
            #pragma unroll
            for (int mf = 0; mf < 2; mf++)
                #pragma unroll
                for (int nf = 0; nf < 8; nf++) {
                    float2 lo = { acc[mf][nf][0], acc[mf][nf][1] };
                    float2 hi = { acc[mf][nf][2], acc[mf][nf][3] };
                    *(float2*)&dist[(r0 + mf*16    )*132 + cb + nf*8] = lo;
                    *(float2*)&dist[(r0 + mf*16 + 8)*132 + cb + nf*8] = hi;
                }
        }
        __syncthreads();

        if (tid < 128) {
            const int cbase = c0 + t*128;
            float worst = td[15];
            #pragma unroll 4
            for (int c = 0; c < 128; c++) {
                float d = snc[c] - 2.0f*dist[tid*132 + c];
                if (d < worst) { topk_insert(td, ti, d, cbase + c); worst = td[15]; }
            }
        }
    }

    if (tid < 128) {
        int q = q0 + tid;
        #pragma unroll
        for (int j = 0; j < 16; j++) {
            g_ptd[(q*KSPL + blockIdx.y)*16 + j] = td[j];
            g_pti[(q*KSPL + blockIdx.y)*16 + j] = ti[j];
        }
    }
}

__global__ void k_merge() {
    int q = blockIdx.x*blockDim.x + threadIdx.x;
    if (q >= NNODES) return;
    float td[16]; int ti[16];
    #pragma unroll
    for (int j = 0; j < 16; j++) { td[j] = 3.0e38f; ti[j] = 0; }
    for (int s = 0; s < KSPL; s++) {
        #pragma unroll
        for (int j = 0; j < 16; j++) {
            float d = g_ptd[(q*KSPL + s)*16 + j];
            int idx = g_pti[(q*KSPL + s)*16 + j];
            topk_insert(td, ti, d, idx);
        }
    }
    #pragma unroll
    for (int j = 0; j < 16; j++) g_knn[q*KNN + j] = ti[j];
}

// ---------------- fused EdgeConv MLP, HMMA bf16-split ----------------
// region0 (reused): A1h/A1l [128][72], W2h/W2l [128n][72]   (GEMM2 inputs)
//                   then W3h/W3l [128n][136]                 (GEMM3 B)
// region1:          A2h/A2l [128][136]                       (GEMM3 A)
#define ESTR1    72
#define ESTR2    136
#define SM_A1H   0
#define SM_A1L   18432
#define SM_W2H   36864
#define SM_W2L   55296
#define SM_W3H   0
#define SM_W3L   34816
#define SM_A2H   73728
#define SM_A2L   108544
#define SM_JIDX  143360
#define EDGE_SMEM (143360 + 512)

__global__ void __launch_bounds__(256) k_edge(
        const float* __restrict__ R, const float* __restrict__ S,
        const float* __restrict__ w2, const float* __restrict__ b2,
        const float* __restrict__ w3, const float* __restrict__ b3,
        float* __restrict__ E)
{
    extern __shared__ char sm[];
    const uint32_t smb = smem_u32(sm);
    const int tid = threadIdx.x, wid = tid >> 5, lane = tid & 31;
    const int wm = wid >> 1, wn = wid & 1;
    const int r0 = blockIdx.x * 128;
    int* jidx = (int*)(sm + SM_JIDX);

    if (tid < 128) jidx[tid] = g_knn[r0 + tid];

    // ---- load W2 transposed + split: w2[k][n] -> W2[n][k] ----
    {
        __nv_bfloat16* W2H = (__nv_bfloat16*)(sm + SM_W2H);
        __nv_bfloat16* W2L = (__nv_bfloat16*)(sm + SM_W2L);
        #pragma unroll
        for (int i = 0; i < 32; i++) {
            int e = tid + i*256;           // 8192 elements
            int k = e >> 7, n = e & 127;
            float v = w2[e];
            __nv_bfloat16 h = __float2bfloat16(v);
            W2H[n*ESTR1 + k] = h;
            W2L[n*ESTR1 + k] = __float2bfloat16(v - __bfloat162float(h));
        }
    }
    __syncthreads();

    // ---- gather H1 = relu(R[i]+S[j]) -> split to A1 ----
    {
        __nv_bfloat16* A1H = (__nv_bfloat16*)(sm + SM_A1H);
        __nv_bfloat16* A1L = (__nv_bfloat16*)(sm + SM_A1L);
        int row = tid >> 1;
        int cb = (tid & 1) * 32;
        int i = (r0 + row) >> 4;
        int j = jidx[row];
        const float* Ri = &R[(size_t)i*64 + cb];
        const float* Sj = &S[(size_t)j*64 + cb];
        #pragma unroll
        for (int c = 0; c < 32; c += 4) {
            float4 rv = *(const float4*)(Ri + c);
            float4 sv = *(const float4*)(Sj + c);
            float h0 = fmaxf(rv.x + sv.x, 0.f), h1 = fmaxf(rv.y + sv.y, 0.f);
            float h2 = fmaxf(rv.z + sv.z, 0.f), h3 = fmaxf(rv.w + sv.w, 0.f);
            __nv_bfloat162 a01 = split_hi2(h0, h1), a23 = split_hi2(h2, h3);
            *(__nv_bfloat162*)&A1H[row*ESTR1 + cb + c]     = a01;
            *(__nv_bfloat162*)&A1H[row*ESTR1 + cb + c + 2] = a23;
            *(__nv_bfloat162*)&A1L[row*ESTR1 + cb + c]     = split_lo2(h0, h1, a01);
            *(__nv_bfloat162*)&A1L[row*ESTR1 + cb + c + 2] = split_lo2(h2, h3, a23);
        }
    }
    __syncthreads();

    const uint32_t a_off2 = (uint32_t)((32*wm + (lane & 15))*ESTR1 + (lane >> 4)*8) * 2;
    const uint32_t b_off2 = (uint32_t)((64*wn + (lane >> 4)*8 + (lane & 7))*ESTR1
                                       + ((lane >> 3) & 1)*8) * 2;

    float acc[2][8][4];
    #pragma unroll
    for (int mf = 0; mf < 2; mf++)
        #pragma unroll
        for (int nf = 0; nf < 8; nf++)
            #pragma unroll
            for (int v = 0; v < 4; v++) acc[mf][nf][v] = 0.f;

    // ---- GEMM2: [128x64] @ [64x128] ----
    #pragma unroll
    for (int term = 0; term < 3; ++term) {
        const uint32_t abase = smb + (term == 2 ? SM_A1L : SM_A1H) + a_off2;
        const uint32_t bbase = smb + (term == 1 ? SM_W2L : SM_W2H) + b_off2;
        #pragma unroll
        for (int ks = 0; ks < 4; ++ks) {
            uint32_t a0[4], a1[4];
            ldm_x4(a0, abase + ks*32);
            ldm_x4(a1, abase + ks*32 + 16*ESTR1*2);
            #pragma unroll
            for (int nf = 0; nf < 4; ++nf) {
                uint32_t b[4];
                ldm_x4(b, bbase + ks*32 + nf*16*ESTR1*2);
                mma16816(acc[0][nf*2],   a0, b);
                mma16816(acc[0][nf*2+1], a0, b + 2);
                mma16816(acc[1][nf*2],   a1, b);
                mma16816(acc[1][nf*2+1], a1, b + 2);
            }
        }
    }
    __syncthreads();   // A1/W2 dead; safe to overwrite region0 with W3

    // ---- epilogue2: bias+relu, split -> A2 ; load W3 transposed ----
    {
        __nv_bfloat16* A2H = (__nv_bfloat16*)(sm + SM_A2H);
        __nv_bfloat16* A2L = (__nv_bfloat16*)(sm + SM_A2L);
        const int re = 32*wm + (lane >> 2);
        const int ce = 64*wn + (lane & 3)*2;
        #pragma unroll
        for (int mf = 0; mf < 2; mf++)
            #pragma unroll
            for (int nf = 0; nf < 8; nf++) {
                int r = re + mf*16;
                int c = ce + nf*8;
                float v0 = fmaxf(acc[mf][nf][0] + b2[c],   0.f);
                float v1 = fmaxf(acc[mf][nf][1] + b2[c+1], 0.f);
                float v2 = fmaxf(acc[mf][nf][2] + b2[c],   0.f);
                float v3 = fmaxf(acc[mf][nf][3] + b2[c+1], 0.f);
                __nv_bfloat162 h01 = split_hi2(v0, v1), h23 = split_hi2(v2, v3);
                *(__nv_bfloat162*)&A2H[r*ESTR2 + c]       = h01;
                *(__nv_bfloat162*)&A2L[r*ESTR2 + c]       = split_lo2(v0, v1, h01);
                *(__nv_bfloat162*)&A2H[(r+8)*ESTR2 + c]   = h23;
                *(__nv_bfloat162*)&A2L[(r+8)*ESTR2 + c]   = split_lo2(v2, v3, h23);
            }
    }
    {
        __nv_bfloat16* W3H = (__nv_bfloat16*)(sm + SM_W3H);
        __nv_bfloat16* W3L = (__nv_bfloat16*)(sm + SM_W3L);
        #pragma unroll
        for (int i = 0; i < 64; i++) {
            int e = tid + i*256;           // 16384 elements
            int k = e >> 7, n = e & 127;
            float v = w3[e];
            __nv_bfloat16 h = __float2bfloat16(v);
            W3H[n*ESTR2 + k] = h;
            W3L[n*ESTR2 + k] = __float2bfloat16(v - __bfloat162float(h));
        }
    }
    __syncthreads();

    // ---- GEMM3: [128x128] @ [128x128] ----
    #pragma unroll
    for (int mf = 0; mf < 2; mf++)
        #pragma unroll
        for (int nf = 0; nf < 8; nf++)
            #pragma unroll
            for (int v = 0; v < 4; v++) acc[mf][nf][v] = 0.f;

    const uint32_t a_off3 = (uint32_t)((32*wm + (lane & 15))*ESTR2 + (lane >> 4)*8) * 2;
    const uint32_t b_off3 = (uint32_t)((64*wn + (lane >> 4)*8 + (lane & 7))*ESTR2
                                       + ((lane >> 3) & 1)*8) * 2;
    #pragma unroll
    for (int term = 0; term < 3; ++term) {
        const uint32_t abase = smb + (term == 2 ? SM_A2L : SM_A2H) + a_off3;
        const uint32_t bbase = smb + (term == 1 ? SM_W3L : SM_W3H) + b_off3;
        #pragma unroll
        for (int ks = 0; ks < 8; ++ks) {
            uint32_t a0[4], a1[4];
            ldm_x4(a0, abase + ks*32);
            ldm_x4(a1, abase + ks*32 + 16*ESTR2*2);
            #pragma unroll
            for (int nf = 0; nf < 4; ++nf) {
                uint32_t b[4];
                ldm_x4(b, bbase + ks*32 + nf*16*ESTR2*2);
                mma16816(acc[0][nf*2],   a0, b);
                mma16816(acc[0][nf*2+1], a0, b + 2);
                mma16816(acc[1][nf*2],   a1, b);
                mma16816(acc[1][nf*2+1], a1, b + 2);
            }
        }
    }

    // ---- maxpool over 16 rows per node (+bias) via shfl ----
    {
        const int ce = 64*wn + (lane & 3)*2;
        #pragma unroll
        for (int mf = 0; mf < 2; mf++) {
            int node = blockIdx.x*8 + 2*wm + mf;
            #pragma unroll
            for (int nf = 0; nf < 8; nf++) {
                float v0 = fmaxf(acc[mf][nf][0], acc[mf][nf][2]);
                float v1 = fmaxf(acc[mf][nf][1], acc[mf][nf][3]);
                #pragma unroll
                for (int o = 4; o < 32; o <<= 1) {
                    v0 = fmaxf(v0, __shfl_xor_sync(0xffffffffu, v0, o));
                    v1 = fmaxf(v1, __shfl_xor_sync(0xffffffffu, v1, o));
                }
                if ((lane >> 2) == 0) {
                    int c = ce + nf*8;
                    E[(size_t)node*128 + c]     = v0 + b3[c];
                    E[(size_t)node*128 + c + 1] = v1 + b3[c+1];
                }
            }
        }
    }
}

// ---------------- SIMT SGEMM (GCN + R/S precompute) ----------------
template<int BN, int TN, int EPI>
__global__ __launch_bounds__(256) void k_gemm(const float* __restrict__ A,
        const float* __restrict__ B, const float* __restrict__ bias,
        float* __restrict__ C, int Kd)
{
    constexpr int BM = 128, BK = 16, TM = 8;
    __shared__ float As[BK][BM + 4];
    __shared__ float Bs[BK][BN + 4];
    const int tid = threadIdx.x;
    const int tx = tid & 15, ty = tid >> 4;
    const int r0 = blockIdx.x * BM;

    float acc[TM][TN];
    #pragma unroll
    for (int m = 0; m < TM; m++)
        #pragma unroll
        for (int n = 0; n < TN; n++) acc[m][n] = 0.f;

    for (int kb = 0; kb < Kd; kb += BK) {
        #pragma unroll
        for (int i = 0; i < 2; i++) {
            int f = tid + i*256;
            int r = f >> 2, c4 = f & 3;
            float4 v = *(const float4*)&A[(size_t)(r0 + r)*Kd + kb + c4*4];
            As[c4*4+0][r] = v.x; As[c4*4+1][r] = v.y;
            As[c4*4+2][r] = v.z; As[c4*4+3][r] = v.w;
        }
        constexpr int BF4 = BK*BN/4;
        #pragma unroll
        for (int i = 0; i < BF4/256; i++) {
            int f = tid + i*256;
            int r = f / (BN/4), c4 = f % (BN/4);
            *(float4*)&Bs[r][c4*4] = *(const float4*)&B[(size_t)(kb + r)*BN + c4*4];
        }
        __syncthreads();
        #pragma unroll
        for (int kk = 0; kk < BK; kk++) {
            float a[TM], b[TN];
            *(float4*)&a[0] = *(const float4*)&As[kk][ty*TM];
            *(float4*)&a[4] = *(const float4*)&As[kk][ty*TM + 4];
            #pragma unroll
            for (int n = 0; n < TN; n += 4)
                *(float4*)&b[n] = *(const float4*)&Bs[kk][tx*TN + n];
            #pragma unroll
            for (int m = 0; m < TM; m++)
                #pragma unroll
                for (int n = 0; n < TN; n++) acc[m][n] += a[m] * b[n];
        }
        __syncthreads();
    }

    #pragma unroll
    for (int m = 0; m < TM; m++) {
        size_t r = r0 + ty*TM + m;
        #pragma unroll
        for (int n = 0; n < TN; n += 4) {
            float4 v;
            v.x = acc[m][n]; v.y = acc[m][n+1]; v.z = acc[m][n+2]; v.w = acc[m][n+3];
            if constexpr (EPI == 1 || EPI == 3) {
                int c = tx*TN + n;
                v.x += bias[c]; v.y += bias[c+1]; v.z += bias[c+2]; v.w += bias[c+3];
                if constexpr (EPI == 1) {
                    v.x = fmaxf(v.x, 0.f); v.y = fmaxf(v.y, 0.f);
                    v.z = fmaxf(v.z, 0.f); v.w = fmaxf(v.w, 0.f);
                }
            }
            *(float4*)&C[r*BN + tx*TN + n] = v;
        }
    }
}

// ---------------- epilogue kernels ----------------
__global__ void k_rownorm() {
    int w = threadIdx.x >> 5, lane = threadIdx.x & 31;
    int i = blockIdx.x*8 + w;
    float4 e = *(const float4*)&g_e[0][i*HDIM + lane*4];
    float4 n = *(const float4*)&g_nbuf[0][i*HDIM + lane*4];
    float a = e.x + n.x, b = e.y + n.y, c = e.z + n.z, d = e.w + n.w;
    float s = a*a + b*b + c*c + d*d;
    #pragma unroll
    for (int o = 16; o; o >>= 1) s += __shfl_xor_sync(0xffffffffu, s, o);
    if (lane == 0) g_r1[i] = sqrtf(s);
}

__global__ void k_final(float* __restrict__ out) {
    int w = threadIdx.x >> 5, lane = threadIdx.x & 31;
    int i = blockIdx.x*8 + w;
    float r = g_r1[i];
    float4 e2 = *(const float4*)&g_e[1][i*HDIM + lane*4];
    float4 n2 = *(const float4*)&g_nbuf[1][i*HDIM + lane*4];
    float4 e3 = *(const float4*)&g_e[2][i*HDIM + lane*4];
    float4 n3 = *(const float4*)&g_nbuf[2][i*HDIM + lane*4];
    float v0 = r * (e2.x + n2.x) * (e3.x + n3.x);
    float v1 = r * (e2.y + n2.y) * (e3.y + n3.y);
    float v2 = r * (e2.z + n2.z) * (e3.z + n3.z);
    float v3 = r * (e2.w + n2.w) * (e3.w + n3.w);
    float m = fmaxf(fmaxf(v0, v1), fmaxf(v2, v3));
    #pragma unroll
    for (int o = 16; o; o >>= 1) m = fmaxf(m, __shfl_xor_sync(0xffffffffu, m, o));
    float s = expf(v0 - m) + expf(v1 - m) + expf(v2 - m) + expf(v3 - m);
    #pragma unroll
    for (int o = 16; o; o >>= 1) s += __shfl_xor_sync(0xffffffffu, s, o);
    float lse = m + logf(s);
    float4 ov = { v0 - lse, v1 - lse, v2 - lse, v3 - lse };
    *(float4*)&out[i*HDIM + lane*4] = ov;
}

// ---------------- launch ----------------
extern "C" void kernel_launch(void* const* d_in, const int* in_sizes, int n_in,
                              void* d_out, int out_size) {
    const float* x  = (const float*)d_in[0];
    const int*   ei = (const int*)  d_in[1];
    const float* ew = (const float*)d_in[2];
    const float* wg[3] = {(const float*)d_in[3], (const float*)d_in[5], (const float*)d_in[7]};
    const float* bg[3] = {(const float*)d_in[4], (const float*)d_in[6], (const float*)d_in[8]};

    float *p_h, *p_n, *p_e, *p_R, *p_S, *p_wd;
    cudaGetSymbolAddress((void**)&p_h,  g_h);
    cudaGetSymbolAddress((void**)&p_n,  g_nbuf);
    cudaGetSymbolAddress((void**)&p_e,  g_e);
    cudaGetSymbolAddress((void**)&p_R,  g_R);
    cudaGetSymbolAddress((void**)&p_S,  g_S);
    cudaGetSymbolAddress((void**)&p_wd, g_wd);

    cudaFuncSetAttribute(k_knn_mma, cudaFuncAttributeMaxDynamicSharedMemorySize, KNN_SMEM);
    cudaFuncSetAttribute(k_edge,    cudaFuncAttributeMaxDynamicSharedMemorySize, EDGE_SMEM);

    // graph prep (once): deg + counts, rsqrt, CSR offsets, placement
    k_deg_init<<<NNODES/256, 256>>>();
    k_deg<<<NEDGE/256, 256>>>(ei, ew);
    k_dis<<<NNODES/256, 256>>>();
    k_scan<<<1, 1024>>>();
    k_place<<<NEDGE/256, 256>>>(ei, ew);

    const float* cur = x;
    for (int L = 0; L < 3; L++) {
        float* nL = p_n + (size_t)L * NNODES * HDIM;
        float* eL = p_e + (size_t)L * NNODES * HDIM;
        const float* w1 = (const float*)d_in[9 + L*6 + 0];
        const float* b1 = (const float*)d_in[9 + L*6 + 1];
        const float* w2 = (const float*)d_in[9 + L*6 + 2];
        const float* b2 = (const float*)d_in[9 + L*6 + 3];
        const float* w3 = (const float*)d_in[9 + L*6 + 4];
        const float* b3 = (const float*)d_in[9 + L*6 + 5];

        // GCN: gemm + fused CSR aggregate/tanh/sn/split
        k_gemm<128,8,0><<<NNODES/128, 256>>>(cur, wg[L], nullptr, p_h, 128);
        k_gather<<<NNODES/8, 256>>>(bg[L], nL);

        // kNN
        k_knn_mma<<<dim3(NNODES/128, KSPL), 256, KNN_SMEM>>>();
        k_merge<<<NNODES/256, 256>>>();

        // EdgeConv: R/S precompute + fused HMMA MLP
        k_wdiff<<<8192/256, 256>>>(w1);
        k_gemm<64,4,3><<<NNODES/128, 256>>>(nL, p_wd,        b1,      p_R, 128);
        k_gemm<64,4,0><<<NNODES/128, 256>>>(nL, w1 + 128*64, nullptr, p_S, 128);
        k_edge<<<NKR/128, 256, EDGE_SMEM>>>(p_R, p_S, w2, b2, w3, b3, eL);

        cur = nL;
    }

    k_rownorm<<<NNODES/8, 256>>>();
    k_final<<<NNODES/8, 256>>>((float*)d_out);
}